// round 16
// baseline (speedup 1.0000x reference)
#include <cuda_runtime.h>
#include <cuda_fp16.h>
#include <stdint.h>

// MX fp8 (e4m3) fake quantization, block=32, shared e8m0 exponent.
//
// Barrier-free per-warp TMA store variant of the R12 champion:
// reads stay 2 x LDG.256 per thread (measured-optimal MLP shape); each warp
// stages its 512-float segment (2KB, contiguous) in SMEM and its elected
// lane issues an independent 2KB UTMASTG right after __syncwarp() -- no
// CTA-wide barrier anywhere, so each warp's write burst starts the moment
// that warp finishes compute instead of waiting for the slowest of 8 warps.
// 2KB contiguous bursts are still far above the 128B-line fragmentation of
// LSU stores (the thing R12 proved costly).
//
// Block amax matters only via its fp32 exponent field (exp-field max ==
// exp field of amax for nonneg floats). e-field==0 (zero/subnormal amax)
// maps to sexp=-127, matching the reference's TINY/clip path.
//
// Element quantization uses the HW e4m3 converter:
//   cvt.rn.satfinite.e4m3x2.f32 == round-half-even onto the e4m3 grid
//   (subnormal step 2^-9, saturate to +-448)
// bit-identical to the reference's priv_exp/pscale/round/clip chain; decode
// is exact via cvt.rn.f16x2.e4m3x2 + f16->f32.

static __device__ __forceinline__ float2 qdq_pair(float x, float y,
                                                  float inv, float scale) {
    float xs = x * inv;                       // exact (power-of-2 scale)
    float ys = y * inv;
    unsigned short p8;
    asm("cvt.rn.satfinite.e4m3x2.f32 %0, %1, %2;"
        : "=h"(p8) : "f"(ys), "f"(xs));       // x -> lo byte
    unsigned h2;
    asm("cvt.rn.f16x2.e4m3x2 %0, %1;" : "=r"(h2) : "h"(p8));
    __half2 hh = *reinterpret_cast<__half2*>(&h2);   // lo=x, hi=y (exact)
    float2 f = __half22float2(hh);
    f.x *= scale;
    f.y *= scale;
    return f;
}

static __device__ __forceinline__ void ldg256_stream(const float* p, float4& a,
                                                     float4& b) {
    asm("ld.global.cs.L2::256B.v8.f32 {%0,%1,%2,%3,%4,%5,%6,%7}, [%8];"
        : "=f"(a.x), "=f"(a.y), "=f"(a.z), "=f"(a.w),
          "=f"(b.x), "=f"(b.y), "=f"(b.z), "=f"(b.w)
        : "l"(p));
}

static __device__ __forceinline__ float amax8(const float4& a,
                                              const float4& b) {
    float m0 = fmaxf(fmaxf(fabsf(a.x), fabsf(a.y)), fmaxf(fabsf(a.z), fabsf(a.w)));
    float m1 = fmaxf(fmaxf(fabsf(b.x), fabsf(b.y)), fmaxf(fabsf(b.z), fabsf(b.w)));
    return fmaxf(m0, m1);
}

__global__ void __launch_bounds__(256) mx_fp8_fq_kernel(
    const float* __restrict__ in, float* __restrict__ out) {
    __shared__ __align__(128) float tile[4096];   // 16KB = 8 x 2KB warp segs

    int tid = threadIdx.x;
    int warp = tid >> 5;
    int lane = tid & 31;
    int local = warp * 512 + lane * 8;            // float offset inside tile
    int cta_base = blockIdx.x * 4096;             // fits 32-bit (n = 2^26)
    const float* pin = in + cta_base + local;

    // Two front-batched 256-bit loads per thread (64B in flight).
    float4 a0, a1, b0, b1;
    ldg256_stream(pin, a0, a1);
    ldg256_stream(pin + 256, b0, b1);

    // Per-load amax -> exponent byte; load A in byte 0, load B in byte 1.
    unsigned packed = (__float_as_uint(amax8(a0, a1)) >> 23)
                    | ((__float_as_uint(amax8(b0, b1)) >> 23) << 8);

    // 4-lane segmented reduction (each v8 load sits inside one quant block).
    packed = __vmaxu4(packed, __shfl_xor_sync(0xffffffffu, packed, 1));
    packed = __vmaxu4(packed, __shfl_xor_sync(0xffffffffu, packed, 2));

#pragma unroll
    for (int j = 0; j < 2; j++) {
        int e = (packed >> (8 * j)) & 0xff;
        int sexp = max(e - 135, -127);   // floor(log2(amax)) - 8, clipped low
        // scale = 2^sexp (sexp==-127 -> subnormal 0x00400000); inv = 2^-sexp.
        float scale = __int_as_float(max((sexp + 127) << 23, 0x00400000));
        float inv   = __int_as_float((127 - sexp) << 23);
        const float4& va = (j == 0) ? a0 : b0;
        const float4& vb = (j == 0) ? a1 : b1;
        float2 p0 = qdq_pair(va.x, va.y, inv, scale);
        float2 p1 = qdq_pair(va.z, va.w, inv, scale);
        float2 p2 = qdq_pair(vb.x, vb.y, inv, scale);
        float2 p3 = qdq_pair(vb.z, vb.w, inv, scale);
        float4* ts = reinterpret_cast<float4*>(&tile[local + 256 * j]);
        ts[0] = make_float4(p0.x, p0.y, p1.x, p1.y);
        ts[1] = make_float4(p2.x, p2.y, p3.x, p3.y);
    }

    // Per-warp epilogue: no CTA barrier. The warp's 2KB segment is complete
    // after __syncwarp(); lane 0 fences and fires an independent bulk store.
    __syncwarp();
    if (lane == 0) {
        unsigned saddr =
            (unsigned)__cvta_generic_to_shared(tile + warp * 512);
        asm volatile("fence.proxy.async.shared::cta;" ::: "memory");
        asm volatile(
            "cp.async.bulk.global.shared::cta.bulk_group [%0], [%1], %2;"
            :: "l"(out + cta_base + warp * 512), "r"(saddr), "r"(2048u)
            : "memory");
        asm volatile("cp.async.bulk.commit_group;" ::: "memory");
        asm volatile("cp.async.bulk.wait_group 0;" ::: "memory");
    }
}

extern "C" void kernel_launch(void* const* d_in, const int* in_sizes, int n_in,
                              void* d_out, int out_size) {
    const float* in = (const float*)d_in[0];
    float* out = (float*)d_out;
    int n = in_sizes[0];              // 8192*8192
    int blocks = n / 4096;            // 16384 CTAs, one 16KB tile each
    mx_fp8_fq_kernel<<<blocks, 256>>>(in, out);
}

// round 17
// speedup vs baseline: 1.0004x; 1.0004x over previous
#include <cuda_runtime.h>
#include <cuda_fp16.h>
#include <stdint.h>

// MX fp8 (e4m3) fake quantization, block=32, shared e8m0 exponent.
//
// FINAL: R12 champion config (best of 16 measured variants) + .read wait.
//   - flat launch, 16384 CTAs x 256 threads, 28 regs, 8 CTAs/SM
//   - reads: 2 x LDG.256 per thread (.cs + L2::256B), 64B in flight --
//     the register-file-optimal MLP point (more bytes costs occupancy)
//   - writes: results staged in a 16KB SMEM tile, ONE 16KB cp.async.bulk
//     (UTMASTG) per CTA -- measured-optimal DRAM write burst size
//     (1KB LSU 74.5us / 2KB 74.3 / 8KB 73.9 / 16KB 73.4 / 32KB 74.0)
//   - epilogue waits with cp.async.bulk.wait_group.read: only the SMEM
//     READ must finish before CTA exit (SMEM recycle safety); the global
//     write completes in flight, freeing the SM slot ~600 cycles earlier.
//
// Block amax matters only via its fp32 exponent field (exp-field max ==
// exp field of amax for nonneg floats). e-field==0 (zero/subnormal amax)
// maps to sexp=-127, matching the reference's TINY/clip path.
//
// Element quantization uses the HW e4m3 converter:
//   cvt.rn.satfinite.e4m3x2.f32 == round-half-even onto the e4m3 grid
//   (subnormal step 2^-9, saturate to +-448)
// bit-identical to the reference's priv_exp/pscale/round/clip chain; decode
// is exact via cvt.rn.f16x2.e4m3x2 + f16->f32.

static __device__ __forceinline__ float2 qdq_pair(float x, float y,
                                                  float inv, float scale) {
    float xs = x * inv;                       // exact (power-of-2 scale)
    float ys = y * inv;
    unsigned short p8;
    asm("cvt.rn.satfinite.e4m3x2.f32 %0, %1, %2;"
        : "=h"(p8) : "f"(ys), "f"(xs));       // x -> lo byte
    unsigned h2;
    asm("cvt.rn.f16x2.e4m3x2 %0, %1;" : "=r"(h2) : "h"(p8));
    __half2 hh = *reinterpret_cast<__half2*>(&h2);   // lo=x, hi=y (exact)
    float2 f = __half22float2(hh);
    f.x *= scale;
    f.y *= scale;
    return f;
}

static __device__ __forceinline__ void ldg256_stream(const float* p, float4& a,
                                                     float4& b) {
    asm("ld.global.cs.L2::256B.v8.f32 {%0,%1,%2,%3,%4,%5,%6,%7}, [%8];"
        : "=f"(a.x), "=f"(a.y), "=f"(a.z), "=f"(a.w),
          "=f"(b.x), "=f"(b.y), "=f"(b.z), "=f"(b.w)
        : "l"(p));
}

static __device__ __forceinline__ float amax8(const float4& a,
                                              const float4& b) {
    float m0 = fmaxf(fmaxf(fabsf(a.x), fabsf(a.y)), fmaxf(fabsf(a.z), fabsf(a.w)));
    float m1 = fmaxf(fmaxf(fabsf(b.x), fabsf(b.y)), fmaxf(fabsf(b.z), fabsf(b.w)));
    return fmaxf(m0, m1);
}

__global__ void __launch_bounds__(256) mx_fp8_fq_kernel(
    const float* __restrict__ in, float* __restrict__ out) {
    __shared__ __align__(128) float tile[4096];   // 16KB staging

    int tid = threadIdx.x;
    int warp = tid >> 5;
    int lane = tid & 31;
    int local = warp * 512 + lane * 8;            // float offset inside tile
    int cta_base = blockIdx.x * 4096;             // fits 32-bit (n = 2^26)
    const float* pin = in + cta_base + local;

    // Two front-batched 256-bit loads per thread (64B in flight).
    float4 a0, a1, b0, b1;
    ldg256_stream(pin, a0, a1);
    ldg256_stream(pin + 256, b0, b1);

    // Per-load amax -> exponent byte; load A in byte 0, load B in byte 1.
    unsigned packed = (__float_as_uint(amax8(a0, a1)) >> 23)
                    | ((__float_as_uint(amax8(b0, b1)) >> 23) << 8);

    // 4-lane segmented reduction (each v8 load sits inside one quant block).
    packed = __vmaxu4(packed, __shfl_xor_sync(0xffffffffu, packed, 1));
    packed = __vmaxu4(packed, __shfl_xor_sync(0xffffffffu, packed, 2));

#pragma unroll
    for (int j = 0; j < 2; j++) {
        int e = (packed >> (8 * j)) & 0xff;
        int sexp = max(e - 135, -127);   // floor(log2(amax)) - 8, clipped low
        // scale = 2^sexp (sexp==-127 -> subnormal 0x00400000); inv = 2^-sexp.
        float scale = __int_as_float(max((sexp + 127) << 23, 0x00400000));
        float inv   = __int_as_float((127 - sexp) << 23);
        const float4& va = (j == 0) ? a0 : b0;
        const float4& vb = (j == 0) ? a1 : b1;
        float2 p0 = qdq_pair(va.x, va.y, inv, scale);
        float2 p1 = qdq_pair(va.z, va.w, inv, scale);
        float2 p2 = qdq_pair(vb.x, vb.y, inv, scale);
        float2 p3 = qdq_pair(vb.z, vb.w, inv, scale);
        float4* ts = reinterpret_cast<float4*>(&tile[local + 256 * j]);
        ts[0] = make_float4(p0.x, p0.y, p1.x, p1.y);
        ts[1] = make_float4(p2.x, p2.y, p3.x, p3.y);
    }

    __syncthreads();

    // One 16KB contiguous bulk store per CTA (UTMASTG path). Wait only for
    // the SMEM read side (.read) -- the global write completes in flight.
    if (tid == 0) {
        unsigned saddr = (unsigned)__cvta_generic_to_shared(tile);
        asm volatile("fence.proxy.async.shared::cta;" ::: "memory");
        asm volatile(
            "cp.async.bulk.global.shared::cta.bulk_group [%0], [%1], %2;"
            :: "l"(out + cta_base), "r"(saddr), "r"(16384u)
            : "memory");
        asm volatile("cp.async.bulk.commit_group;" ::: "memory");
        asm volatile("cp.async.bulk.wait_group.read 0;" ::: "memory");
    }
}

extern "C" void kernel_launch(void* const* d_in, const int* in_sizes, int n_in,
                              void* d_out, int out_size) {
    const float* in = (const float*)d_in[0];
    float* out = (float*)d_out;
    int n = in_sizes[0];              // 8192*8192
    int blocks = n / 4096;            // 16384 CTAs, one 16KB tile each
    mx_fp8_fq_kernel<<<blocks, 256>>>(in, out);
}